// round 16
// baseline (speedup 1.0000x reference)
#include <cuda_runtime.h>

#define FULL 0xffffffffu
typedef unsigned long long u64;

// ---------------------------------------------------------------------------
// Half-warp (16 lanes) per item, 2 items/warp (2048 warps — the proven floor).
// Full 8-qubit state: 256 amps = 16 lanes x 16 local amps.
// Slot (lg, j): wire w<4 -> bit w of j (local), wire w>=4 -> bit (w-4) of lg.
// Packed (re,im) u64 everywhere. Cross phase in phase-twisted b-rep.
// R14: ring L1 layers = per-lane 3-cmul product tree (0 shuffles).
// R16: fast-intrinsic setup trig; packed two-accumulator sumD in measurement.
// ---------------------------------------------------------------------------

__device__ __forceinline__ u64 pk(float a, float b) {
    u64 r; asm("mov.b64 %0,{%1,%2};" : "=l"(r) : "f"(a), "f"(b)); return r;
}
__device__ __forceinline__ float2 upk(u64 v) {
    float2 r; asm("mov.b64 {%0,%1},%2;" : "=f"(r.x), "=f"(r.y) : "l"(v)); return r;
}
__device__ __forceinline__ u64 dupp(float a) { return pk(a, a); }
__device__ __forceinline__ u64 swapp(u64 v) { float2 h = upk(v); return pk(h.y, h.x); }
__device__ __forceinline__ u64 f2mul(u64 a, u64 b) {
    u64 r; asm("mul.rn.f32x2 %0,%1,%2;" : "=l"(r) : "l"(a), "l"(b)); return r;
}
__device__ __forceinline__ u64 f2fma(u64 a, u64 b, u64 c) {
    u64 r; asm("fma.rn.f32x2 %0,%1,%2,%3;" : "=l"(r) : "l"(a), "l"(b), "l"(c)); return r;
}
__device__ __forceinline__ u64 negp(u64 v) { return v ^ 0x8000000080000000ULL; }
__device__ __forceinline__ u64 neghi(u64 v) { return v ^ 0x8000000000000000ULL; }

// packed complex multiply: (a.x,a.y)*(b.x,b.y) as one u64
__device__ __forceinline__ u64 cmulp(u64 A, u64 B) {
    float2 a = upk(A);
    return f2fma(dupp(a.x), B, f2mul(pk(-a.y, a.y), swapp(B)));
}

__device__ __forceinline__ u64 shflpx(u64 v, int m) {  // xor-shuffle both halves
    float2 h = upk(v);
    h.x = __shfl_xor_sync(FULL, h.x, m);
    h.y = __shfl_xor_sync(FULL, h.y, m);
    return pk(h.x, h.y);
}

// Segmented butterfly: reduce 8 per-lane floats over the 16-lane group.
__device__ __forceinline__ float segred8(const float* v, int lg) {
    const bool b3 = lg & 8, b2 = lg & 4, b1 = lg & 2;
    float s0 = b3 ? v[0] : v[4];
    float s1 = b3 ? v[1] : v[5];
    float s2 = b3 ? v[2] : v[6];
    float s3 = b3 ? v[3] : v[7];
    s0 = __shfl_xor_sync(FULL, s0, 8);
    s1 = __shfl_xor_sync(FULL, s1, 8);
    s2 = __shfl_xor_sync(FULL, s2, 8);
    s3 = __shfl_xor_sync(FULL, s3, 8);
    float n0 = (b3 ? v[4] : v[0]) + s0;
    float n1 = (b3 ? v[5] : v[1]) + s1;
    float n2 = (b3 ? v[6] : v[2]) + s2;
    float n3 = (b3 ? v[7] : v[3]) + s3;
    float t0 = b2 ? n0 : n2;
    float t1 = b2 ? n1 : n3;
    t0 = __shfl_xor_sync(FULL, t0, 4);
    t1 = __shfl_xor_sync(FULL, t1, 4);
    n0 = (b2 ? n2 : n0) + t0;
    n1 = (b2 ? n3 : n1) + t1;
    float u0 = b1 ? n0 : n1;
    u0 = __shfl_xor_sync(FULL, u0, 2);
    n0 = (b1 ? n1 : n0) + u0;
    n0 += __shfl_xor_sync(FULL, n0, 1);
    return n0;
}

// packed rxmix on (re,im): new = dupp(c)*A + pk(s,-s)*swap(T)
__device__ __forceinline__ u64 rxpp(u64 A, u64 T, float c, float s) {
    return f2fma(pk(s, -s), swapp(T), f2mul(dupp(c), A));
}

// packed general unitary [[u00,u01],[-conj(u01),conj(u00)]], own bit b
__device__ __forceinline__ u64 genpp(u64 A, u64 T, float4 u, int b) {
    float cy = b ? -u.y : u.y;
    float dx = b ? -u.z : u.z;
    return f2fma(dupp(u.x), A,
           f2fma(pk(-cy, cy), swapp(A),
           f2fma(dupp(dx), T,
           f2mul(pk(-u.w, u.w), swapp(T)))));
}

// fuse data RX into constant GEN triple: U = GEN @ RX(theta)
__device__ __forceinline__ float4 fuse_rx(float4 g, float c, float s) {
    return make_float4(c * g.x + s * g.w, c * g.y - s * g.z,
                       c * g.z + s * g.y, c * g.w - s * g.x);
}

// first column of U applied to |0>, selected by this lane's wire bit
__device__ __forceinline__ u64 col0sel(float4 u, int bit) {
    return bit ? pk(-u.z, u.w) : pk(u.x, u.y);
}

// ---------------------------------------------------------------------------

__global__ void __launch_bounds__(64, 7)
qa_fused(const float* __restrict__ x_text, const float* __restrict__ x_image,
         const float* __restrict__ W_text, const float* __restrict__ b_text,
         const float* __restrict__ W_image, const float* __restrict__ b_image,
         const float* __restrict__ qr, const float* __restrict__ qc,
         const float* __restrict__ kr, const float* __restrict__ kc,
         const float* __restrict__ vr, const float* __restrict__ vc,
         const float* __restrict__ cr, const float* __restrict__ cc,
         const float* __restrict__ cc2, const float* __restrict__ gates,
         float* __restrict__ out, int B, int IN) {
    __shared__ float4 sf[28];
    __shared__ float2 scs[40];
    __shared__ float sgates[4];
    __shared__ float4 szm[4];  // (p, m.x, m.y, r)
    __shared__ float2 sn[4];   // (n.x, n.y)

    for (int t = threadIdx.x; t < 76; t += blockDim.x) {
        if (t < 28) {
            int grp = t >> 2, i = t & 3;
            float a = 0.f, b = 0.f, c = 0.f;
            switch (grp) {
                case 0: a = qr[3 * i];      b = qr[3 * i + 1];      c = qr[3 * i + 2];      break;
                case 1: a = qr[12 + 3 * i]; b = qr[12 + 3 * i + 1]; c = qr[12 + 3 * i + 2]; break;
                case 2: a = kr[3 * i];      b = kr[3 * i + 1];      c = kr[3 * i + 2];      break;
                case 3: a = kr[12 + 3 * i]; b = kr[12 + 3 * i + 1]; c = kr[12 + 3 * i + 2]; break;
                case 4: a = cr[3 * i];      b = cr[3 * i + 1];      c = cr[3 * i + 2];      break;
                case 5: a = vr[3 * i];      b = vr[3 * i + 1];      c = vr[3 * i + 2];      break;
                case 6: a = vr[12 + 3 * i]; b = vr[12 + 3 * i + 1]; c = vr[12 + 3 * i + 2]; break;
            }
            float cb, sb, csum, ssum, cdif, sdif;
            __sincosf(0.5f * b, &sb, &cb);
            __sincosf(0.5f * (a + c), &ssum, &csum);
            __sincosf(0.5f * (a - c), &sdif, &cdif);
            sf[t] = make_float4(cb * csum, -cb * ssum, sb * sdif, -sb * cdif);
        } else if (t < 68) {
            int u = t - 28;
            float p;
            if (u < 8) p = qc[u];
            else if (u < 16) p = kc[u - 8];
            else if (u < 24) p = cc[u - 16];
            else if (u < 32) p = cc2[u - 24];
            else p = vc[u - 32];
            float s, c;
            __sincosf(0.5f * p, &s, &c);
            scs[u] = make_float2(c, s);
        } else if (t < 72) {
            sgates[t - 68] = gates[t - 68];
        } else {
            int i = t - 72;
            float aa = cr[3 * i], b = cr[3 * i + 1], c = cr[3 * i + 2];
            float cb, sb, csum, ssum, cdif, sdif;
            __sincosf(0.5f * b, &sb, &cb);
            __sincosf(0.5f * (aa + c), &ssum, &csum);
            __sincosf(0.5f * (aa - c), &sdif, &cdif);
            float alx = cb * csum, aly = -cb * ssum;
            float bex = sb * sdif, bey = -sb * cdif;
            float p = alx * alx + aly * aly - bex * bex - bey * bey;
            float mx = 2.f * (alx * bex + aly * bey);
            float my = 2.f * (alx * bey - aly * bex);
            float r = -2.f * (alx * bex - aly * bey);
            float nx = (alx * alx - aly * aly) - (bex * bex - bey * bey);
            float ny = -2.f * alx * aly - 2.f * bex * bey;
            szm[i] = make_float4(p, mx, my, r);
            sn[i] = make_float2(nx, ny);
        }
    }
    __syncthreads();

    const int lane = threadIdx.x & 31;
    const int half = lane >> 4;
    const int lg = lane & 15;
    const int gbase = lane & 16;
    const int wsel = ((lg >> 2) & 1) * 2 + ((lg >> 1) & 1);
    const int gw = (int)((blockIdx.x * blockDim.x + threadIdx.x) >> 5);
    const int item = gw * 2 + half;
    const int itc = item < B ? item : (B - 1);

    // ---- projections: UNROLLED (IN=96), segmented reduce, 1 sincos, broadcast ----
    float cqv[4], sqv[4], ckv[4], skv[4];
    {
        const float2* xt2 = (const float2*)(x_text + (long)itc * IN);
        const float2* xi2 = (const float2*)(x_image + (long)itc * IN);
        const int hin = IN >> 1;
        float pv[8] = {0.f, 0.f, 0.f, 0.f, 0.f, 0.f, 0.f, 0.f};
#define PROJ_STEP(KK) { const int k = lg + (KK);                              \
        float2 xa = __ldg(&xt2[k]);                                           \
        float2 xb = __ldg(&xi2[k]);                                           \
        _Pragma("unroll")                                                     \
        for (int r = 0; r < 4; r++) {                                         \
            float2 wa = __ldg((const float2*)(W_text + r * IN) + k);          \
            float2 wb = __ldg((const float2*)(W_image + r * IN) + k);         \
            pv[r]     += xa.x * wa.x + xa.y * wa.y;                           \
            pv[4 + r] += xb.x * wb.x + xb.y * wb.y;                           \
        } }
        if (hin == 48) { PROJ_STEP(0) PROJ_STEP(16) PROJ_STEP(32) }
        else { for (int k0 = 0; k0 < hin; k0 += 16) if (lg + k0 < hin) { PROJ_STEP(k0) } }
#undef PROJ_STEP
        float xval = segred8(pv, lg);
        const bool gk = lg & 8;
        xval += __ldg((gk ? b_image : b_text) + wsel);
        float s_ang, c_ang;
        __sincosf(0.5f * xval, &s_ang, &c_ang);
#pragma unroll
        for (int i = 0; i < 4; i++) {
            cqv[i] = __shfl_sync(FULL, c_ang, gbase | (2 * i));
            sqv[i] = __shfl_sync(FULL, s_ang, gbase | (2 * i));
            ckv[i] = __shfl_sync(FULL, c_ang, gbase | 8 | (2 * i));
            skv[i] = __shfl_sync(FULL, s_ang, gbase | 8 | (2 * i));
        }
    }

    // ---- product phase: L1 layers via per-lane product tree (0 shuffles) ----
    u64 Q, K, V;
    {
        u64 sq[4], sk[4], sv[4];
#pragma unroll
        for (int i = 0; i < 4; i++) {
            const int b = (lg >> i) & 1;
            sq[i] = col0sel(fuse_rx(sf[i],      cqv[i], sqv[i]), b);
            sk[i] = col0sel(fuse_rx(sf[8 + i],  ckv[i], skv[i]), b);
            sv[i] = col0sel(fuse_rx(sf[20 + i], ckv[i], skv[i]), b);
        }
        Q = cmulp(cmulp(sq[0], sq[1]), cmulp(sq[2], sq[3]));
        K = cmulp(cmulp(sk[0], sk[1]), cmulp(sk[2], sk[3]));
        V = cmulp(cmulp(sv[0], sv[1]), cmulp(sv[2], sv[3]));
    }

#pragma unroll
    for (int i = 0; i < 4; i++) {  // CRX rings (branchless coefficient select)
        const int m = 1 << ((i + 1) & 3);
        const bool p = (lg >> i) & 1;
        float cq = p ? scs[i].x : 1.f,      sq = p ? scs[i].y : 0.f;
        float ck = p ? scs[8 + i].x : 1.f,  sk = p ? scs[8 + i].y : 0.f;
        float cv = p ? scs[32 + i].x : 1.f, sv = p ? scs[32 + i].y : 0.f;
        u64 tq = shflpx(Q, m), tk = shflpx(K, m), tv = shflpx(V, m);
        Q = rxpp(Q, tq, cq, sq);
        K = rxpp(K, tk, ck, sk);
        V = rxpp(V, tv, cv, sv);
    }
#pragma unroll
    for (int i = 0; i < 4; i++) {  // IsingXX rings
        const int m = (1 << i) | (1 << ((i + 1) & 3));
        u64 tq = shflpx(Q, m), tk = shflpx(K, m), tv = shflpx(V, m);
        Q = rxpp(Q, tq, scs[4 + i].x, scs[4 + i].y);
        K = rxpp(K, tk, scs[12 + i].x, scs[12 + i].y);
        V = rxpp(V, tv, scs[36 + i].x, scs[36 + i].y);
    }
#pragma unroll
    for (int i = 0; i < 4; i++) {  // L2 rot layers (constant gates)
        const int b = (lg >> i) & 1;
        const int m = 1 << i;
        u64 tq = shflpx(Q, m), tk = shflpx(K, m), tv = shflpx(V, m);
        Q = genpp(Q, tq, sf[4 + i], b);
        K = genpp(K, tk, sf[12 + i], b);
        V = genpp(V, tv, sf[24 + i], b);
    }

    // ---- assemble full state in b-rep: sigma twist on Q, then packed cmul ----
    u64 A[16];
    {
        int pop = __popc(lg);
        bool p1 = pop & 1, p2 = pop & 2;
        u64 t = p1 ? neghi(swapp(Q)) : Q;     // *(-i): (re,im)->(im,-re)
        u64 Q2 = p2 ? negp(t) : t;
        float2 q2 = upk(Q2);
        u64 Ksw = swapp(K);
#pragma unroll
        for (int j = 0; j < 16; j++) {
            float qre = __shfl_sync(FULL, q2.x, j, 16);
            float qim = __shfl_sync(FULL, q2.y, j, 16);
            A[j] = f2fma(dupp(qre), K, f2mul(pk(-qim, qim), Ksw));
        }
    }

    // ---- cross entanglers in b-rep (packed; verified R10) ----
    // CRX(i,4+i): local ctrl -> lane target (complex rxmix)
#pragma unroll
    for (int i = 0; i < 4; i++) {
        const u64 C2 = dupp(scs[16 + i].x), S2 = pk(scs[16 + i].y, -scs[16 + i].y);
        const int ml = 1 << i;
#pragma unroll
        for (int j = 0; j < 16; j++)
            if ((j >> i) & 1) {
                float2 h = upk(A[j]);
                float tx = __shfl_xor_sync(FULL, h.x, ml);
                float ty = __shfl_xor_sync(FULL, h.y, ml);
                A[j] = f2fma(S2, pk(ty, tx), f2mul(C2, A[j]));
            }
    }
    // CRX(4+i,i): lane ctrl -> local target (REAL rotation in b-rep)
#pragma unroll
    for (int i = 0; i < 4; i++) {
        const bool e = (lg >> i) & 1;
        const float c = e ? scs[20 + i].x : 1.f, s = e ? scs[20 + i].y : 0.f;
        const u64 C2 = dupp(c), S2 = dupp(s), N2 = dupp(-s);
        const int m = 1 << i;
#pragma unroll
        for (int j = 0; j < 16; j++)
            if (!(j & m)) {
                u64 b0 = A[j], b1 = A[j | m];
                A[j]     = f2fma(S2, b1, f2mul(C2, b0));
                A[j | m] = f2fma(N2, b0, f2mul(C2, b1));
            }
    }
    // CRX2(i, ((i+1)&3)+4): local ctrl -> lane target
#pragma unroll
    for (int i = 0; i < 4; i++) {
        const u64 C2 = dupp(scs[24 + i].x), S2 = pk(scs[24 + i].y, -scs[24 + i].y);
        const int ml = 1 << ((i + 1) & 3);
#pragma unroll
        for (int j = 0; j < 16; j++)
            if ((j >> i) & 1) {
                float2 h = upk(A[j]);
                float tx = __shfl_xor_sync(FULL, h.x, ml);
                float ty = __shfl_xor_sync(FULL, h.y, ml);
                A[j] = f2fma(S2, pk(ty, tx), f2mul(C2, A[j]));
            }
    }
    // CRX2(4+i, (i+1)&3): lane ctrl -> local target (real rotation)
#pragma unroll
    for (int i = 0; i < 4; i++) {
        const bool e = (lg >> i) & 1;
        const float c = e ? scs[28 + i].x : 1.f, s = e ? scs[28 + i].y : 0.f;
        const u64 C2 = dupp(c), S2 = dupp(s), N2 = dupp(-s);
        const int m = 1 << ((i + 1) & 3);
#pragma unroll
        for (int j = 0; j < 16; j++)
            if (!(j & m)) {
                u64 b0 = A[j], b1 = A[j | m];
                A[j]     = f2fma(S2, b1, f2mul(C2, b0));
                A[j | m] = f2fma(N2, b0, f2mul(C2, b1));
            }
    }
    // all 4 CNOT(i,4+i): one dynamic-src shuffle stage
#pragma unroll
    for (int j = 0; j < 16; j++) {
        float2 h = upk(A[j]);
        int src = gbase | (lg ^ j);
        h.x = __shfl_sync(FULL, h.x, src);
        h.y = __shfl_sync(FULL, h.y, src);
        A[j] = pk(h.x, h.y);
    }
    // all 4 CNOT(4+i,i): FREE via basis relabel (slot j holds basis j^lg).

    // ---- measurement: factored coefficients; packed two-accumulator sumD ----
    float cc0[4], ss0[4];
    {
        float acc[8];
#pragma unroll
        for (int w = 0; w < 4; w++) {
            const int m = 1 << w;
            u64 sRI = 0ULL;      // packed (sumRb, sumIb)
            u64 sD0 = 0ULL, sD1 = 0ULL;
#pragma unroll
            for (int j = 0; j < 16; j++) {
                if (j & m) continue;
                u64 A0 = A[j], A1 = A[j | m];
                float2 e0 = upk(A0);
                sD0 = f2fma(A0, A0, sD0);
                sD1 = f2fma(A1, A1, sD1);
                sRI = f2fma(pk(e0.y, -e0.y), swapp(A1), f2fma(dupp(e0.x), A1, sRI));
            }
            float2 RI = upk(sRI);
            float2 d0 = upk(sD0), d1 = upk(sD1);
            float sumD = (d0.x + d0.y) - (d1.x + d1.y);
            const float4 zm = szm[w];
            const float2 nn = sn[w];
            const float sgn = ((lg >> w) & 1) ? -1.f : 1.f;
            acc[w]     = sgn * (zm.x * sumD - 2.f * zm.z * RI.x) - 2.f * zm.y * RI.y;
            acc[4 + w] = sgn * (zm.w * sumD - 2.f * nn.y * RI.x) - 2.f * nn.x * RI.y;
        }
        float S = segred8(acc, lg);
        float other = __shfl_xor_sync(FULL, S, 8);
        float amp = sqrtf(S * S + other * other);
        float ang = tanhf(amp) * sgates[wsel];
        float ss_l, cc_l;
        __sincosf(0.5f * ang, &ss_l, &cc_l);
#pragma unroll
        for (int i = 0; i < 4; i++) {
            cc0[i] = __shfl_sync(FULL, cc_l, gbase | (2 * i));
            ss0[i] = __shfl_sync(FULL, ss_l, gbase | (2 * i));
        }
    }

    // ---- value tail: amp-RX fused pairwise, packed ----
    {
        {   // wires 0,1 (masks 1,2)
            float AB = cc0[0] * cc0[1], AsB = cc0[0] * ss0[1],
                  sAB = ss0[0] * cc0[1], ss = ss0[0] * ss0[1];
            u64 T0 = shflpx(V, 1), T1 = shflpx(V, 2), T2 = shflpx(V, 3);
            V = f2fma(dupp(AB), V,
                f2fma(pk(sAB, -sAB), swapp(T0),
                f2fma(pk(AsB, -AsB), swapp(T1),
                f2mul(dupp(-ss), T2))));
        }
        {   // wires 2,3 (masks 4,8)
            float AB = cc0[2] * cc0[3], AsB = cc0[2] * ss0[3],
                  sAB = ss0[2] * cc0[3], ss = ss0[2] * ss0[3];
            u64 T0 = shflpx(V, 4), T1 = shflpx(V, 8), T2 = shflpx(V, 12);
            V = f2fma(dupp(AB), V,
                f2fma(pk(sAB, -sAB), swapp(T0),
                f2fma(pk(AsB, -AsB), swapp(T1),
                f2mul(dupp(-ss), T2))));
        }
    }
    // CNOT ring folded into measurement via basis permutation pi
    int pi = lg;
    pi ^= (pi & 1) << 1;
    pi ^= ((pi >> 1) & 1) << 2;
    pi ^= ((pi >> 2) & 1) << 3;
    pi ^= (pi >> 3) & 1;

    // ---- final measurement: segmented reduce + direct scatter store ----
    {
        float2 vv = upk(V);
        float ov[8];
        const float nv = vv.x * vv.x + vv.y * vv.y;
#pragma unroll
        for (int w = 0; w < 4; w++) ov[w] = ((pi >> w) & 1) ? -nv : nv;
#pragma unroll
        for (int w = 0; w < 4; w++) {
            int r = pi ^ (1 << w);
            r ^= (r >> 3) & 1;
            r ^= ((r >> 2) & 1) << 3;
            r ^= ((r >> 1) & 1) << 2;
            r ^= (r & 1) << 1;
            float tx = __shfl_sync(FULL, vv.x, gbase | r);
            float ty = __shfl_sync(FULL, vv.y, gbase | r);
            ov[4 + w] = vv.x * tx + vv.y * ty;
        }
        float oS = segred8(ov, lg);
        const int oidx = ((lg >> 3) & 1) * 4 + wsel;
        if (!(lg & 1) && item < B)
            out[(long)item * 8 + oidx] = oS;
    }
}

// ---------------------------------------------------------------------------

extern "C" void kernel_launch(void* const* d_in, const int* in_sizes, int n_in,
                              void* d_out, int out_size) {
    const float* x_text  = (const float*)d_in[0];
    const float* x_image = (const float*)d_in[1];
    const float* W_text  = (const float*)d_in[2];
    const float* b_text  = (const float*)d_in[3];
    const float* W_image = (const float*)d_in[4];
    const float* b_image = (const float*)d_in[5];
    const float* q_rot   = (const float*)d_in[6];
    const float* q_crx   = (const float*)d_in[7];
    const float* k_rot   = (const float*)d_in[8];
    const float* k_crx   = (const float*)d_in[9];
    const float* v_rot   = (const float*)d_in[10];
    const float* v_crx   = (const float*)d_in[11];
    const float* c_rot   = (const float*)d_in[12];
    const float* c_crx   = (const float*)d_in[13];
    const float* c_crx2  = (const float*)d_in[14];
    const float* gates   = (const float*)d_in[15];

    int IN = in_sizes[2] / 4;   // W_text is [4, IN]
    int B  = in_sizes[0] / IN;  // x_text is [B, IN]

    int nwarps = (B + 1) / 2;   // 2 items per warp
    int threads = 64;
    int blocks = (nwarps * 32 + threads - 1) / threads;
    qa_fused<<<blocks, threads>>>(x_text, x_image, W_text, b_text, W_image, b_image,
                                  q_rot, q_crx, k_rot, k_crx, v_rot, v_crx,
                                  c_rot, c_crx, c_crx2, gates,
                                  (float*)d_out, B, IN);
}

// round 17
// speedup vs baseline: 1.0429x; 1.0429x over previous
#include <cuda_runtime.h>

#define FULL 0xffffffffu
typedef unsigned long long u64;

// ---------------------------------------------------------------------------
// Half-warp (16 lanes) per item, 2 items/warp (2048 warps — the proven floor).
// Full 8-qubit state: 256 amps = 16 lanes x 16 local amps.
// Slot (lg, j): wire w<4 -> bit w of j (local), wire w>=4 -> bit (w-4) of lg.
// Packed (re,im) u64 everywhere. Cross phase in phase-twisted b-rep.
// R14: ring L1 layers = per-lane 3-cmul product tree (0 shuffles).
// R16: fast-intrinsic setup trig; packed two-accumulator sumD.
// R17: swap-half folded INTO the shuffle (shflpxsw) in rings + value tail.
// ---------------------------------------------------------------------------

__device__ __forceinline__ u64 pk(float a, float b) {
    u64 r; asm("mov.b64 %0,{%1,%2};" : "=l"(r) : "f"(a), "f"(b)); return r;
}
__device__ __forceinline__ float2 upk(u64 v) {
    float2 r; asm("mov.b64 {%0,%1},%2;" : "=f"(r.x), "=f"(r.y) : "l"(v)); return r;
}
__device__ __forceinline__ u64 dupp(float a) { return pk(a, a); }
__device__ __forceinline__ u64 swapp(u64 v) { float2 h = upk(v); return pk(h.y, h.x); }
__device__ __forceinline__ u64 f2mul(u64 a, u64 b) {
    u64 r; asm("mul.rn.f32x2 %0,%1,%2;" : "=l"(r) : "l"(a), "l"(b)); return r;
}
__device__ __forceinline__ u64 f2fma(u64 a, u64 b, u64 c) {
    u64 r; asm("fma.rn.f32x2 %0,%1,%2,%3;" : "=l"(r) : "l"(a), "l"(b), "l"(c)); return r;
}
__device__ __forceinline__ u64 negp(u64 v) { return v ^ 0x8000000080000000ULL; }
__device__ __forceinline__ u64 neghi(u64 v) { return v ^ 0x8000000000000000ULL; }

// packed complex multiply: (a.x,a.y)*(b.x,b.y) as one u64
__device__ __forceinline__ u64 cmulp(u64 A, u64 B) {
    float2 a = upk(A);
    return f2fma(dupp(a.x), B, f2mul(pk(-a.y, a.y), swapp(B)));
}

__device__ __forceinline__ u64 shflpx(u64 v, int m) {  // xor-shuffle both halves
    float2 h = upk(v);
    h.x = __shfl_xor_sync(FULL, h.x, m);
    h.y = __shfl_xor_sync(FULL, h.y, m);
    return pk(h.x, h.y);
}
// xor-shuffle, delivering the SWAPPED pair (im, re) directly — no MOVs
__device__ __forceinline__ u64 shflpxsw(u64 v, int m) {
    float2 h = upk(v);
    float lo = __shfl_xor_sync(FULL, h.y, m);
    float hi = __shfl_xor_sync(FULL, h.x, m);
    return pk(lo, hi);
}

// Segmented butterfly: reduce 8 per-lane floats over the 16-lane group.
__device__ __forceinline__ float segred8(const float* v, int lg) {
    const bool b3 = lg & 8, b2 = lg & 4, b1 = lg & 2;
    float s0 = b3 ? v[0] : v[4];
    float s1 = b3 ? v[1] : v[5];
    float s2 = b3 ? v[2] : v[6];
    float s3 = b3 ? v[3] : v[7];
    s0 = __shfl_xor_sync(FULL, s0, 8);
    s1 = __shfl_xor_sync(FULL, s1, 8);
    s2 = __shfl_xor_sync(FULL, s2, 8);
    s3 = __shfl_xor_sync(FULL, s3, 8);
    float n0 = (b3 ? v[4] : v[0]) + s0;
    float n1 = (b3 ? v[5] : v[1]) + s1;
    float n2 = (b3 ? v[6] : v[2]) + s2;
    float n3 = (b3 ? v[7] : v[3]) + s3;
    float t0 = b2 ? n0 : n2;
    float t1 = b2 ? n1 : n3;
    t0 = __shfl_xor_sync(FULL, t0, 4);
    t1 = __shfl_xor_sync(FULL, t1, 4);
    n0 = (b2 ? n2 : n0) + t0;
    n1 = (b2 ? n3 : n1) + t1;
    float u0 = b1 ? n0 : n1;
    u0 = __shfl_xor_sync(FULL, u0, 2);
    n0 = (b1 ? n1 : n0) + u0;
    n0 += __shfl_xor_sync(FULL, n0, 1);
    return n0;
}

// packed rxmix with PRE-SWAPPED partner: new = dupp(c)*A + pk(s,-s)*Tsw
__device__ __forceinline__ u64 rxppw(u64 A, u64 Tsw, float c, float s) {
    return f2fma(pk(s, -s), Tsw, f2mul(dupp(c), A));
}

// packed general unitary [[u00,u01],[-conj(u01),conj(u00)]], own bit b
__device__ __forceinline__ u64 genpp(u64 A, u64 T, float4 u, int b) {
    float cy = b ? -u.y : u.y;
    float dx = b ? -u.z : u.z;
    return f2fma(dupp(u.x), A,
           f2fma(pk(-cy, cy), swapp(A),
           f2fma(dupp(dx), T,
           f2mul(pk(-u.w, u.w), swapp(T)))));
}

// fuse data RX into constant GEN triple: U = GEN @ RX(theta)
__device__ __forceinline__ float4 fuse_rx(float4 g, float c, float s) {
    return make_float4(c * g.x + s * g.w, c * g.y - s * g.z,
                       c * g.z + s * g.y, c * g.w - s * g.x);
}

// first column of U applied to |0>, selected by this lane's wire bit
__device__ __forceinline__ u64 col0sel(float4 u, int bit) {
    return bit ? pk(-u.z, u.w) : pk(u.x, u.y);
}

// ---------------------------------------------------------------------------

__global__ void __launch_bounds__(64, 7)
qa_fused(const float* __restrict__ x_text, const float* __restrict__ x_image,
         const float* __restrict__ W_text, const float* __restrict__ b_text,
         const float* __restrict__ W_image, const float* __restrict__ b_image,
         const float* __restrict__ qr, const float* __restrict__ qc,
         const float* __restrict__ kr, const float* __restrict__ kc,
         const float* __restrict__ vr, const float* __restrict__ vc,
         const float* __restrict__ cr, const float* __restrict__ cc,
         const float* __restrict__ cc2, const float* __restrict__ gates,
         float* __restrict__ out, int B, int IN) {
    __shared__ float4 sf[28];
    __shared__ float2 scs[40];
    __shared__ float sgates[4];
    __shared__ float4 szm[4];  // (p, m.x, m.y, r)
    __shared__ float2 sn[4];   // (n.x, n.y)

    for (int t = threadIdx.x; t < 76; t += blockDim.x) {
        if (t < 28) {
            int grp = t >> 2, i = t & 3;
            float a = 0.f, b = 0.f, c = 0.f;
            switch (grp) {
                case 0: a = qr[3 * i];      b = qr[3 * i + 1];      c = qr[3 * i + 2];      break;
                case 1: a = qr[12 + 3 * i]; b = qr[12 + 3 * i + 1]; c = qr[12 + 3 * i + 2]; break;
                case 2: a = kr[3 * i];      b = kr[3 * i + 1];      c = kr[3 * i + 2];      break;
                case 3: a = kr[12 + 3 * i]; b = kr[12 + 3 * i + 1]; c = kr[12 + 3 * i + 2]; break;
                case 4: a = cr[3 * i];      b = cr[3 * i + 1];      c = cr[3 * i + 2];      break;
                case 5: a = vr[3 * i];      b = vr[3 * i + 1];      c = vr[3 * i + 2];      break;
                case 6: a = vr[12 + 3 * i]; b = vr[12 + 3 * i + 1]; c = vr[12 + 3 * i + 2]; break;
            }
            float cb, sb, csum, ssum, cdif, sdif;
            __sincosf(0.5f * b, &sb, &cb);
            __sincosf(0.5f * (a + c), &ssum, &csum);
            __sincosf(0.5f * (a - c), &sdif, &cdif);
            sf[t] = make_float4(cb * csum, -cb * ssum, sb * sdif, -sb * cdif);
        } else if (t < 68) {
            int u = t - 28;
            float p;
            if (u < 8) p = qc[u];
            else if (u < 16) p = kc[u - 8];
            else if (u < 24) p = cc[u - 16];
            else if (u < 32) p = cc2[u - 24];
            else p = vc[u - 32];
            float s, c;
            __sincosf(0.5f * p, &s, &c);
            scs[u] = make_float2(c, s);
        } else if (t < 72) {
            sgates[t - 68] = gates[t - 68];
        } else {
            int i = t - 72;
            float aa = cr[3 * i], b = cr[3 * i + 1], c = cr[3 * i + 2];
            float cb, sb, csum, ssum, cdif, sdif;
            __sincosf(0.5f * b, &sb, &cb);
            __sincosf(0.5f * (aa + c), &ssum, &csum);
            __sincosf(0.5f * (aa - c), &sdif, &cdif);
            float alx = cb * csum, aly = -cb * ssum;
            float bex = sb * sdif, bey = -sb * cdif;
            float p = alx * alx + aly * aly - bex * bex - bey * bey;
            float mx = 2.f * (alx * bex + aly * bey);
            float my = 2.f * (alx * bey - aly * bex);
            float r = -2.f * (alx * bex - aly * bey);
            float nx = (alx * alx - aly * aly) - (bex * bex - bey * bey);
            float ny = -2.f * alx * aly - 2.f * bex * bey;
            szm[i] = make_float4(p, mx, my, r);
            sn[i] = make_float2(nx, ny);
        }
    }
    __syncthreads();

    const int lane = threadIdx.x & 31;
    const int half = lane >> 4;
    const int lg = lane & 15;
    const int gbase = lane & 16;
    const int wsel = ((lg >> 2) & 1) * 2 + ((lg >> 1) & 1);
    const int gw = (int)((blockIdx.x * blockDim.x + threadIdx.x) >> 5);
    const int item = gw * 2 + half;
    const int itc = item < B ? item : (B - 1);

    // ---- projections: UNROLLED (IN=96), segmented reduce, 1 sincos, broadcast ----
    float cqv[4], sqv[4], ckv[4], skv[4];
    {
        const float2* xt2 = (const float2*)(x_text + (long)itc * IN);
        const float2* xi2 = (const float2*)(x_image + (long)itc * IN);
        const int hin = IN >> 1;
        float pv[8] = {0.f, 0.f, 0.f, 0.f, 0.f, 0.f, 0.f, 0.f};
#define PROJ_STEP(KK) { const int k = lg + (KK);                              \
        float2 xa = __ldg(&xt2[k]);                                           \
        float2 xb = __ldg(&xi2[k]);                                           \
        _Pragma("unroll")                                                     \
        for (int r = 0; r < 4; r++) {                                         \
            float2 wa = __ldg((const float2*)(W_text + r * IN) + k);          \
            float2 wb = __ldg((const float2*)(W_image + r * IN) + k);         \
            pv[r]     += xa.x * wa.x + xa.y * wa.y;                           \
            pv[4 + r] += xb.x * wb.x + xb.y * wb.y;                           \
        } }
        if (hin == 48) { PROJ_STEP(0) PROJ_STEP(16) PROJ_STEP(32) }
        else { for (int k0 = 0; k0 < hin; k0 += 16) if (lg + k0 < hin) { PROJ_STEP(k0) } }
#undef PROJ_STEP
        float xval = segred8(pv, lg);
        const bool gk = lg & 8;
        xval += __ldg((gk ? b_image : b_text) + wsel);
        float s_ang, c_ang;
        __sincosf(0.5f * xval, &s_ang, &c_ang);
#pragma unroll
        for (int i = 0; i < 4; i++) {
            cqv[i] = __shfl_sync(FULL, c_ang, gbase | (2 * i));
            sqv[i] = __shfl_sync(FULL, s_ang, gbase | (2 * i));
            ckv[i] = __shfl_sync(FULL, c_ang, gbase | 8 | (2 * i));
            skv[i] = __shfl_sync(FULL, s_ang, gbase | 8 | (2 * i));
        }
    }

    // ---- product phase: L1 layers via per-lane product tree (0 shuffles) ----
    u64 Q, K, V;
    {
        u64 sq[4], sk[4], sv[4];
#pragma unroll
        for (int i = 0; i < 4; i++) {
            const int b = (lg >> i) & 1;
            sq[i] = col0sel(fuse_rx(sf[i],      cqv[i], sqv[i]), b);
            sk[i] = col0sel(fuse_rx(sf[8 + i],  ckv[i], skv[i]), b);
            sv[i] = col0sel(fuse_rx(sf[20 + i], ckv[i], skv[i]), b);
        }
        Q = cmulp(cmulp(sq[0], sq[1]), cmulp(sq[2], sq[3]));
        K = cmulp(cmulp(sk[0], sk[1]), cmulp(sk[2], sk[3]));
        V = cmulp(cmulp(sv[0], sv[1]), cmulp(sv[2], sv[3]));
    }

#pragma unroll
    for (int i = 0; i < 4; i++) {  // CRX rings (branchless; swap folded into shfl)
        const int m = 1 << ((i + 1) & 3);
        const bool p = (lg >> i) & 1;
        float cq = p ? scs[i].x : 1.f,      sq = p ? scs[i].y : 0.f;
        float ck = p ? scs[8 + i].x : 1.f,  sk = p ? scs[8 + i].y : 0.f;
        float cv = p ? scs[32 + i].x : 1.f, sv = p ? scs[32 + i].y : 0.f;
        u64 tq = shflpxsw(Q, m), tk = shflpxsw(K, m), tv = shflpxsw(V, m);
        Q = rxppw(Q, tq, cq, sq);
        K = rxppw(K, tk, ck, sk);
        V = rxppw(V, tv, cv, sv);
    }
#pragma unroll
    for (int i = 0; i < 4; i++) {  // IsingXX rings (swap folded into shfl)
        const int m = (1 << i) | (1 << ((i + 1) & 3));
        u64 tq = shflpxsw(Q, m), tk = shflpxsw(K, m), tv = shflpxsw(V, m);
        Q = rxppw(Q, tq, scs[4 + i].x, scs[4 + i].y);
        K = rxppw(K, tk, scs[12 + i].x, scs[12 + i].y);
        V = rxppw(V, tv, scs[36 + i].x, scs[36 + i].y);
    }
#pragma unroll
    for (int i = 0; i < 4; i++) {  // L2 rot layers (constant gates)
        const int b = (lg >> i) & 1;
        const int m = 1 << i;
        u64 tq = shflpx(Q, m), tk = shflpx(K, m), tv = shflpx(V, m);
        Q = genpp(Q, tq, sf[4 + i], b);
        K = genpp(K, tk, sf[12 + i], b);
        V = genpp(V, tv, sf[24 + i], b);
    }

    // ---- assemble full state in b-rep: sigma twist on Q, then packed cmul ----
    u64 A[16];
    {
        int pop = __popc(lg);
        bool p1 = pop & 1, p2 = pop & 2;
        u64 t = p1 ? neghi(swapp(Q)) : Q;     // *(-i): (re,im)->(im,-re)
        u64 Q2 = p2 ? negp(t) : t;
        float2 q2 = upk(Q2);
        u64 Ksw = swapp(K);
#pragma unroll
        for (int j = 0; j < 16; j++) {
            float qre = __shfl_sync(FULL, q2.x, j, 16);
            float qim = __shfl_sync(FULL, q2.y, j, 16);
            A[j] = f2fma(dupp(qre), K, f2mul(pk(-qim, qim), Ksw));
        }
    }

    // ---- cross entanglers in b-rep (packed; verified R10) ----
    // CRX(i,4+i): local ctrl -> lane target (complex rxmix; swapped gather)
#pragma unroll
    for (int i = 0; i < 4; i++) {
        const u64 C2 = dupp(scs[16 + i].x), S2 = pk(scs[16 + i].y, -scs[16 + i].y);
        const int ml = 1 << i;
#pragma unroll
        for (int j = 0; j < 16; j++)
            if ((j >> i) & 1) {
                u64 tsw = shflpxsw(A[j], ml);
                A[j] = f2fma(S2, tsw, f2mul(C2, A[j]));
            }
    }
    // CRX(4+i,i): lane ctrl -> local target (REAL rotation in b-rep)
#pragma unroll
    for (int i = 0; i < 4; i++) {
        const bool e = (lg >> i) & 1;
        const float c = e ? scs[20 + i].x : 1.f, s = e ? scs[20 + i].y : 0.f;
        const u64 C2 = dupp(c), S2 = dupp(s), N2 = dupp(-s);
        const int m = 1 << i;
#pragma unroll
        for (int j = 0; j < 16; j++)
            if (!(j & m)) {
                u64 b0 = A[j], b1 = A[j | m];
                A[j]     = f2fma(S2, b1, f2mul(C2, b0));
                A[j | m] = f2fma(N2, b0, f2mul(C2, b1));
            }
    }
    // CRX2(i, ((i+1)&3)+4): local ctrl -> lane target
#pragma unroll
    for (int i = 0; i < 4; i++) {
        const u64 C2 = dupp(scs[24 + i].x), S2 = pk(scs[24 + i].y, -scs[24 + i].y);
        const int ml = 1 << ((i + 1) & 3);
#pragma unroll
        for (int j = 0; j < 16; j++)
            if ((j >> i) & 1) {
                u64 tsw = shflpxsw(A[j], ml);
                A[j] = f2fma(S2, tsw, f2mul(C2, A[j]));
            }
    }
    // CRX2(4+i, (i+1)&3): lane ctrl -> local target (real rotation)
#pragma unroll
    for (int i = 0; i < 4; i++) {
        const bool e = (lg >> i) & 1;
        const float c = e ? scs[28 + i].x : 1.f, s = e ? scs[28 + i].y : 0.f;
        const u64 C2 = dupp(c), S2 = dupp(s), N2 = dupp(-s);
        const int m = 1 << ((i + 1) & 3);
#pragma unroll
        for (int j = 0; j < 16; j++)
            if (!(j & m)) {
                u64 b0 = A[j], b1 = A[j | m];
                A[j]     = f2fma(S2, b1, f2mul(C2, b0));
                A[j | m] = f2fma(N2, b0, f2mul(C2, b1));
            }
    }
    // all 4 CNOT(i,4+i): one dynamic-src shuffle stage
#pragma unroll
    for (int j = 0; j < 16; j++) {
        float2 h = upk(A[j]);
        int src = gbase | (lg ^ j);
        h.x = __shfl_sync(FULL, h.x, src);
        h.y = __shfl_sync(FULL, h.y, src);
        A[j] = pk(h.x, h.y);
    }
    // all 4 CNOT(4+i,i): FREE via basis relabel (slot j holds basis j^lg).

    // ---- measurement: factored coefficients; packed two-accumulator sumD ----
    float cc0[4], ss0[4];
    {
        float acc[8];
#pragma unroll
        for (int w = 0; w < 4; w++) {
            const int m = 1 << w;
            u64 sRI = 0ULL;      // packed (sumRb, sumIb)
            u64 sD0 = 0ULL, sD1 = 0ULL;
#pragma unroll
            for (int j = 0; j < 16; j++) {
                if (j & m) continue;
                u64 A0 = A[j], A1 = A[j | m];
                float2 e0 = upk(A0);
                sD0 = f2fma(A0, A0, sD0);
                sD1 = f2fma(A1, A1, sD1);
                sRI = f2fma(pk(e0.y, -e0.y), swapp(A1), f2fma(dupp(e0.x), A1, sRI));
            }
            float2 RI = upk(sRI);
            float2 d0 = upk(sD0), d1 = upk(sD1);
            float sumD = (d0.x + d0.y) - (d1.x + d1.y);
            const float4 zm = szm[w];
            const float2 nn = sn[w];
            const float sgn = ((lg >> w) & 1) ? -1.f : 1.f;
            acc[w]     = sgn * (zm.x * sumD - 2.f * zm.z * RI.x) - 2.f * zm.y * RI.y;
            acc[4 + w] = sgn * (zm.w * sumD - 2.f * nn.y * RI.x) - 2.f * nn.x * RI.y;
        }
        float S = segred8(acc, lg);
        float other = __shfl_xor_sync(FULL, S, 8);
        float amp = sqrtf(S * S + other * other);
        float ang = tanhf(amp) * sgates[wsel];
        float ss_l, cc_l;
        __sincosf(0.5f * ang, &ss_l, &cc_l);
#pragma unroll
        for (int i = 0; i < 4; i++) {
            cc0[i] = __shfl_sync(FULL, cc_l, gbase | (2 * i));
            ss0[i] = __shfl_sync(FULL, ss_l, gbase | (2 * i));
        }
    }

    // ---- value tail: amp-RX fused pairwise (swap folded into shfl) ----
    {
        {   // wires 0,1 (masks 1,2)
            float AB = cc0[0] * cc0[1], AsB = cc0[0] * ss0[1],
                  sAB = ss0[0] * cc0[1], ss = ss0[0] * ss0[1];
            u64 T0 = shflpxsw(V, 1), T1 = shflpxsw(V, 2), T2 = shflpx(V, 3);
            V = f2fma(dupp(AB), V,
                f2fma(pk(sAB, -sAB), T0,
                f2fma(pk(AsB, -AsB), T1,
                f2mul(dupp(-ss), T2))));
        }
        {   // wires 2,3 (masks 4,8)
            float AB = cc0[2] * cc0[3], AsB = cc0[2] * ss0[3],
                  sAB = ss0[2] * cc0[3], ss = ss0[2] * ss0[3];
            u64 T0 = shflpxsw(V, 4), T1 = shflpxsw(V, 8), T2 = shflpx(V, 12);
            V = f2fma(dupp(AB), V,
                f2fma(pk(sAB, -sAB), T0,
                f2fma(pk(AsB, -AsB), T1,
                f2mul(dupp(-ss), T2))));
        }
    }
    // CNOT ring folded into measurement via basis permutation pi
    int pi = lg;
    pi ^= (pi & 1) << 1;
    pi ^= ((pi >> 1) & 1) << 2;
    pi ^= ((pi >> 2) & 1) << 3;
    pi ^= (pi >> 3) & 1;

    // ---- final measurement: segmented reduce + direct scatter store ----
    {
        float2 vv = upk(V);
        float ov[8];
        const float nv = vv.x * vv.x + vv.y * vv.y;
#pragma unroll
        for (int w = 0; w < 4; w++) ov[w] = ((pi >> w) & 1) ? -nv : nv;
#pragma unroll
        for (int w = 0; w < 4; w++) {
            int r = pi ^ (1 << w);
            r ^= (r >> 3) & 1;
            r ^= ((r >> 2) & 1) << 3;
            r ^= ((r >> 1) & 1) << 2;
            r ^= (r & 1) << 1;
            float tx = __shfl_sync(FULL, vv.x, gbase | r);
            float ty = __shfl_sync(FULL, vv.y, gbase | r);
            ov[4 + w] = vv.x * tx + vv.y * ty;
        }
        float oS = segred8(ov, lg);
        const int oidx = ((lg >> 3) & 1) * 4 + wsel;
        if (!(lg & 1) && item < B)
            out[(long)item * 8 + oidx] = oS;
    }
}

// ---------------------------------------------------------------------------

extern "C" void kernel_launch(void* const* d_in, const int* in_sizes, int n_in,
                              void* d_out, int out_size) {
    const float* x_text  = (const float*)d_in[0];
    const float* x_image = (const float*)d_in[1];
    const float* W_text  = (const float*)d_in[2];
    const float* b_text  = (const float*)d_in[3];
    const float* W_image = (const float*)d_in[4];
    const float* b_image = (const float*)d_in[5];
    const float* q_rot   = (const float*)d_in[6];
    const float* q_crx   = (const float*)d_in[7];
    const float* k_rot   = (const float*)d_in[8];
    const float* k_crx   = (const float*)d_in[9];
    const float* v_rot   = (const float*)d_in[10];
    const float* v_crx   = (const float*)d_in[11];
    const float* c_rot   = (const float*)d_in[12];
    const float* c_crx   = (const float*)d_in[13];
    const float* c_crx2  = (const float*)d_in[14];
    const float* gates   = (const float*)d_in[15];

    int IN = in_sizes[2] / 4;   // W_text is [4, IN]
    int B  = in_sizes[0] / IN;  // x_text is [B, IN]

    int nwarps = (B + 1) / 2;   // 2 items per warp
    int threads = 64;
    int blocks = (nwarps * 32 + threads - 1) / threads;
    qa_fused<<<blocks, threads>>>(x_text, x_image, W_text, b_text, W_image, b_image,
                                  q_rot, q_crx, k_rot, k_crx, v_rot, v_crx,
                                  c_rot, c_crx, c_crx2, gates,
                                  (float*)d_out, B, IN);
}